// round 14
// baseline (speedup 1.0000x reference)
#include <cuda_runtime.h>
#include <cuda_fp16.h>
#include <cuda_pipeline.h>
#include <mma.h>
#include <stdint.h>

using namespace nvcuda;

#define B_  4
#define L_  2048
#define D_  1024
#define H_  16
#define DH_ 64
#define M_  (B_*L_)
#define BH_ (B_*H_)
#define SCALE 0.5f
#define PT 40      // fp16 tile pitch (halves): 80B = conflict-free LDSM
#define PV 72      // V tile pitch (halves): 144B = conflict-free LDSM

typedef __half hf;

// ---------------- static scratch ----------------
__device__ hf g_Oh[(size_t)M_*D_];              // PV output, fp16
__device__ hf g_Qh[(size_t)BH_*L_*DH_];
__device__ hf g_Ql[(size_t)BH_*L_*DH_];
__device__ hf g_Kh[(size_t)BH_*L_*DH_];
__device__ hf g_Kl[(size_t)BH_*L_*DH_];
__device__ hf g_V [(size_t)BH_*L_*DH_];
__device__ hf g_attnh[(size_t)BH_*L_*L_];       // fp16 normalized attn copy
__device__ hf g_Wth[4][(size_t)D_*D_];          // W^T hi: [n][k]
__device__ hf g_Wtl[4][(size_t)D_*D_];          // lo used only for Wq, Wk
__device__ float g_attn_fallback[(size_t)BH_*L_*L_];

__device__ __forceinline__ void split1h(float x, unsigned short& h, unsigned short& l){
    hf hb = __float2half_rn(x);
    float r = x - __half2float(hb);
    hf lb = __float2half_rn(r);
    h = __half_as_ushort(hb);
    l = __half_as_ushort(lb);
}

// ---- register-prefetch A tile: fp32 [128 x 32] ----
struct ARegs { float4 v[4]; };

__device__ __forceinline__ void fetch_a(ARegs& r, const float* __restrict__ X, int ldx,
                                        int row0, int k0, int tid){
    #pragma unroll
    for (int i = 0; i < 4; i++) {
        int e = tid + i*256;
        int m = e >> 3, k4 = (e & 7) << 2;
        r.v[i] = *(const float4*)(X + (size_t)(row0+m)*ldx + k0 + k4);
    }
}
__device__ __forceinline__ void store_a_split(const ARegs& r, hf* dh, hf* dl, int tid){
    #pragma unroll
    for (int i = 0; i < 4; i++) {
        int e = tid + i*256;
        int m = e >> 3, k4 = (e & 7) << 2;
        unsigned short h0,h1,h2,h3,l0,l1,l2,l3;
        split1h(r.v[i].x,h0,l0); split1h(r.v[i].y,h1,l1);
        split1h(r.v[i].z,h2,l2); split1h(r.v[i].w,h3,l3);
        uint2 hp = make_uint2((uint32_t)h0 | ((uint32_t)h1<<16), (uint32_t)h2 | ((uint32_t)h3<<16));
        uint2 lp = make_uint2((uint32_t)l0 | ((uint32_t)l1<<16), (uint32_t)l2 | ((uint32_t)l3<<16));
        *(uint2*)(dh + m*PT + k4) = hp;
        *(uint2*)(dl + m*PT + k4) = lp;
    }
}
__device__ __forceinline__ void store_a_round(const ARegs& r, hf* d, int tid){
    #pragma unroll
    for (int i = 0; i < 4; i++) {
        int e = tid + i*256;
        int m = e >> 3, k4 = (e & 7) << 2;
        __half2 p0 = __floats2half2_rn(r.v[i].x, r.v[i].y);
        __half2 p1 = __floats2half2_rn(r.v[i].z, r.v[i].w);
        uint2 u;
        u.x = *(uint32_t*)&p0;
        u.y = *(uint32_t*)&p1;
        *(uint2*)(d + m*PT + k4) = u;
    }
}

// async copy fp16 [128 x 32] tile (pitch PT)
__device__ __forceinline__ void async_b(int tid, const hf* __restrict__ G, int ld,
                                        int row0, int k0, hf* dst){
    #pragma unroll
    for (int i = 0; i < 2; i++) {
        int e = tid + i*256;
        int rr = e >> 2, o = e & 3;
        __pipeline_memcpy_async(dst + rr*PT + o*8,
                                G + (size_t)(row0+rr)*ld + k0 + o*8, 16);
    }
}
// async copy fp16 [32 x 64] V tile (pitch PV)
__device__ __forceinline__ void async_v(int tid, const hf* __restrict__ G,
                                        int k0, hf* dst){
    int rr = tid >> 3, o = tid & 7;
    __pipeline_memcpy_async(dst + rr*PV + o*8,
                            G + (size_t)(k0+rr)*DH_ + o*8, 16);
}
// plain fp16 [128 x 32] copy (pitch PT)
__device__ __forceinline__ void load_rows_h(int tid, const hf* __restrict__ G, int ld,
                                            int row0, int k0, hf* dst){
    #pragma unroll
    for (int i = 0; i < 2; i++) {
        int e = tid + i*256;
        int rr = e >> 2, o = e & 3;
        uint4 v = *(const uint4*)(G + (size_t)(row0+rr)*ld + k0 + o*8);
        *(uint4*)(dst + rr*PT + o*8) = v;
    }
}

// ============================================================================
// Weight split+transpose: all 4 weights in one launch (z selects)
// ============================================================================
__global__ __launch_bounds__(256) void split_w4_kernel(
    const float* __restrict__ W0, const float* __restrict__ W1,
    const float* __restrict__ W2, const float* __restrict__ W3,
    hf* __restrict__ ohBase, hf* __restrict__ olBase)
{
    const int z = blockIdx.z;
    const float* W = (z == 0) ? W0 : (z == 1) ? W1 : (z == 2) ? W2 : W3;
    hf* oh = ohBase + (size_t)z * D_ * D_;
    hf* ol = olBase + (size_t)z * D_ * D_;
    __shared__ float s[32][33];
    const int bk = blockIdx.x*32, bn = blockIdx.y*32;
    const int tx = threadIdx.x & 31, ty = threadIdx.x >> 5;
    #pragma unroll
    for (int i = 0; i < 4; i++)
        s[ty + i*8][tx] = W[(size_t)(bk + ty + i*8)*D_ + bn + tx];
    __syncthreads();
    #pragma unroll
    for (int i = 0; i < 4; i++) {
        float v = s[tx][ty + i*8];
        unsigned short h, l; split1h(v, h, l);
        size_t a = (size_t)(bn + ty + i*8)*D_ + bk + tx;
        oh[a] = __ushort_as_half(h);
        ol[a] = __ushort_as_half(l);
    }
}

// ============================================================================
// Q+K projections fused via blockIdx.z (3-term fp16, head-split hi/lo out)
// ============================================================================
__global__ __launch_bounds__(256, 2) void proj_qk(
    const float* __restrict__ qin, const float* __restrict__ kin,
    const hf* __restrict__ Wth0, const hf* __restrict__ Wtl0,
    const hf* __restrict__ Wth1, const hf* __restrict__ Wtl1,
    const float* __restrict__ bq, const float* __restrict__ bk,
    hf* __restrict__ Qh, hf* __restrict__ Ql,
    hf* __restrict__ Kh, hf* __restrict__ Kl)
{
    const int z = blockIdx.z;
    const float* X   = z ? kin  : qin;
    const hf* Wth    = z ? Wth1 : Wth0;
    const hf* Wtl    = z ? Wtl1 : Wtl0;
    const float* bias= z ? bk   : bq;
    hf* outH         = z ? Kh   : Qh;
    hf* outL         = z ? Kl   : Ql;

    extern __shared__ char sm[];
    const int BT = 128*PT;
    hf* Ah  = (hf*)sm;
    hf* Al  = Ah + BT;
    hf* Bh0 = Al + BT;
    hf* Bl0 = Bh0 + BT;
    hf* Bh1 = Bl0 + BT;
    hf* Bl1 = Bh1 + BT;
    const int tid = threadIdx.x, w = tid >> 5, lid = tid & 31;
    const int wm = w >> 2, wn = w & 3;
    const int bm = blockIdx.y * 128, bn = blockIdx.x * 128;

    wmma::fragment<wmma::accumulator, 16, 16, 16, float> acc[4][2];
    #pragma unroll
    for (int i = 0; i < 4; i++)
        #pragma unroll
        for (int j = 0; j < 2; j++)
            wmma::fill_fragment(acc[i][j], 0.0f);

    async_b(tid, Wth, D_, bn, 0, Bh0);
    async_b(tid, Wtl, D_, bn, 0, Bl0);
    __pipeline_commit();
    ARegs ra;
    fetch_a(ra, X, D_, bm, 0, tid);

    for (int t = 0; t < 32; t++) {
        hf* Bhc = (t & 1) ? Bh1 : Bh0;
        hf* Blc = (t & 1) ? Bl1 : Bl0;
        if (t+1 < 32) {
            hf* Bhn = (t & 1) ? Bh0 : Bh1;
            hf* Bln = (t & 1) ? Bl0 : Bl1;
            async_b(tid, Wth, D_, bn, (t+1)*32, Bhn);
            async_b(tid, Wtl, D_, bn, (t+1)*32, Bln);
            __pipeline_commit();
        }
        store_a_split(ra, Ah, Al, tid);
        if (t+1 < 32) __pipeline_wait_prior(1);
        else          __pipeline_wait_prior(0);
        __syncthreads();
        if (t+1 < 32) fetch_a(ra, X, D_, bm, (t+1)*32, tid);

        #pragma unroll
        for (int ks = 0; ks < 32; ks += 16) {
            wmma::fragment<wmma::matrix_b, 16, 16, 16, hf, wmma::col_major> fbh[2], fbl[2];
            #pragma unroll
            for (int j = 0; j < 2; j++) {
                wmma::load_matrix_sync(fbh[j], Bhc + (wn*32 + j*16)*PT + ks, PT);
                wmma::load_matrix_sync(fbl[j], Blc + (wn*32 + j*16)*PT + ks, PT);
            }
            #pragma unroll
            for (int i = 0; i < 4; i++) {
                wmma::fragment<wmma::matrix_a, 16, 16, 16, hf, wmma::row_major> fah, fal;
                wmma::load_matrix_sync(fah, Ah + (wm*64 + i*16)*PT + ks, PT);
                wmma::load_matrix_sync(fal, Al + (wm*64 + i*16)*PT + ks, PT);
                #pragma unroll
                for (int j = 0; j < 2; j++) {
                    wmma::mma_sync(acc[i][j], fah, fbh[j], acc[i][j]);
                    wmma::mma_sync(acc[i][j], fah, fbl[j], acc[i][j]);
                    wmma::mma_sync(acc[i][j], fal, fbh[j], acc[i][j]);
                }
            }
        }
        __syncthreads();
    }

    float* ws = (float*)sm + w * (16*24);
    hf* SH = (hf*)(sm + 12288);
    hf* SL = (hf*)(sm + 12288 + 34816);
    #pragma unroll
    for (int i = 0; i < 4; i++) {
        #pragma unroll
        for (int j = 0; j < 2; j++) {
            wmma::store_matrix_sync(ws, acc[i][j], 24, wmma::mem_row_major);
            __syncwarp();
            #pragma unroll
            for (int tt = 0; tt < 8; tt++) {
                int e = lid + tt*32, r = e >> 4, c = e & 15;
                int row = wm*64 + i*16 + r;
                int col = wn*32 + j*16 + c;
                float v = ws[r*24 + c] + bias[bn + col];
                unsigned short hs, ls; split1h(v, hs, ls);
                SH[row*136 + col] = __ushort_as_half(hs);
                SL[row*136 + col] = __ushort_as_half(ls);
            }
            __syncwarp();
        }
    }
    __syncthreads();
    #pragma unroll
    for (int q = 0; q < 8; q++) {
        int e = tid + q*256;
        int rr = e >> 4, o = e & 15;
        int m = bm + rr, bb = m >> 11, l = m & (L_-1);
        int n0 = bn + o*8, h = n0 >> 6, dh = n0 & 63;
        size_t a = (((size_t)(bb*H_ + h))*L_ + l)*DH_ + dh;
        *(uint4*)(outH + a) = *(uint4*)(&SH[rr*136 + o*8]);
        *(uint4*)(outL + a) = *(uint4*)(&SL[rr*136 + o*8]);
    }
}

// ============================================================================
// V projection (1-term, head-split fp16 out)
// ============================================================================
__global__ __launch_bounds__(256, 2) void proj_v(
    const float* __restrict__ X,
    const hf* __restrict__ Wth, const float* __restrict__ bias,
    hf* __restrict__ outH)
{
    extern __shared__ char sm[];
    const int BT = 128*PT;
    hf* Ah  = (hf*)sm;
    hf* Bh0 = Ah + BT;
    hf* Bh1 = Bh0 + BT;
    const int tid = threadIdx.x, w = tid >> 5, lid = tid & 31;
    const int wm = w >> 2, wn = w & 3;
    const int bm = blockIdx.y * 128, bn = blockIdx.x * 128;

    wmma::fragment<wmma::accumulator, 16, 16, 16, float> acc[4][2];
    #pragma unroll
    for (int i = 0; i < 4; i++)
        #pragma unroll
        for (int j = 0; j < 2; j++)
            wmma::fill_fragment(acc[i][j], 0.0f);

    async_b(tid, Wth, D_, bn, 0, Bh0);
    __pipeline_commit();
    ARegs ra;
    fetch_a(ra, X, D_, bm, 0, tid);

    for (int t = 0; t < 32; t++) {
        hf* Bhc = (t & 1) ? Bh1 : Bh0;
        if (t+1 < 32) {
            hf* Bhn = (t & 1) ? Bh0 : Bh1;
            async_b(tid, Wth, D_, bn, (t+1)*32, Bhn);
            __pipeline_commit();
        }
        store_a_round(ra, Ah, tid);
        if (t+1 < 32) __pipeline_wait_prior(1);
        else          __pipeline_wait_prior(0);
        __syncthreads();
        if (t+1 < 32) fetch_a(ra, X, D_, bm, (t+1)*32, tid);

        #pragma unroll
        for (int ks = 0; ks < 32; ks += 16) {
            wmma::fragment<wmma::matrix_b, 16, 16, 16, hf, wmma::col_major> fbh[2];
            #pragma unroll
            for (int j = 0; j < 2; j++)
                wmma::load_matrix_sync(fbh[j], Bhc + (wn*32 + j*16)*PT + ks, PT);
            #pragma unroll
            for (int i = 0; i < 4; i++) {
                wmma::fragment<wmma::matrix_a, 16, 16, 16, hf, wmma::row_major> fah;
                wmma::load_matrix_sync(fah, Ah + (wm*64 + i*16)*PT + ks, PT);
                #pragma unroll
                for (int j = 0; j < 2; j++)
                    wmma::mma_sync(acc[i][j], fah, fbh[j], acc[i][j]);
            }
        }
        __syncthreads();
    }

    float* ws = (float*)sm + w * (16*24);
    hf* SH = (hf*)(sm + 12288);
    #pragma unroll
    for (int i = 0; i < 4; i++) {
        #pragma unroll
        for (int j = 0; j < 2; j++) {
            wmma::store_matrix_sync(ws, acc[i][j], 24, wmma::mem_row_major);
            __syncwarp();
            #pragma unroll
            for (int tt = 0; tt < 8; tt++) {
                int e = lid + tt*32, r = e >> 4, c = e & 15;
                int row = wm*64 + i*16 + r;
                int col = wn*32 + j*16 + c;
                SH[row*136 + col] = __float2half_rn(ws[r*24 + c] + bias[bn + col]);
            }
            __syncwarp();
        }
    }
    __syncthreads();
    #pragma unroll
    for (int q = 0; q < 8; q++) {
        int e = tid + q*256;
        int rr = e >> 4, o = e & 15;
        int m = bm + rr, bb = m >> 11, l = m & (L_-1);
        int n0 = bn + o*8, h = n0 >> 6, dh = n0 & 63;
        size_t a = (((size_t)(bb*H_ + h))*L_ + l)*DH_ + dh;
        *(uint4*)(outH + a) = *(uint4*)(&SH[rr*136 + o*8]);
    }
}

// ============================================================================
// Scores: attn_raw = SCALE * Q @ K^T, 3-term fp16 — float4 direct-write epilogue
// ============================================================================
__global__ __launch_bounds__(256, 2) void scores_mma(float* __restrict__ attn)
{
    extern __shared__ char sm[];
    hf* Ah = (hf*)sm;
    hf* Al = Ah + 128*PT;
    hf* Bh = Al + 128*PT;
    hf* Bl = Bh + 128*PT;
    const int tid = threadIdx.x, w = tid >> 5, lid = tid & 31;
    const int wm = w >> 2, wn = w & 3;
    const int bh = blockIdx.z, bm = blockIdx.y * 128, bn = blockIdx.x * 128;
    const size_t qo = (size_t)bh * L_ * DH_;

    wmma::fragment<wmma::accumulator, 16, 16, 16, float> acc[4][2];
    #pragma unroll
    for (int i = 0; i < 4; i++)
        #pragma unroll
        for (int j = 0; j < 2; j++)
            wmma::fill_fragment(acc[i][j], 0.0f);

    #pragma unroll
    for (int t = 0; t < 2; t++) {
        load_rows_h(tid, g_Qh + qo, DH_, bm, t*32, Ah);
        load_rows_h(tid, g_Ql + qo, DH_, bm, t*32, Al);
        load_rows_h(tid, g_Kh + qo, DH_, bn, t*32, Bh);
        load_rows_h(tid, g_Kl + qo, DH_, bn, t*32, Bl);
        __syncthreads();
        #pragma unroll
        for (int ks = 0; ks < 32; ks += 16) {
            wmma::fragment<wmma::matrix_b, 16, 16, 16, hf, wmma::col_major> fbh[2], fbl[2];
            #pragma unroll
            for (int j = 0; j < 2; j++) {
                wmma::load_matrix_sync(fbh[j], Bh + (wn*32 + j*16)*PT + ks, PT);
                wmma::load_matrix_sync(fbl[j], Bl + (wn*32 + j*16)*PT + ks, PT);
            }
            #pragma unroll
            for (int i = 0; i < 4; i++) {
                wmma::fragment<wmma::matrix_a, 16, 16, 16, hf, wmma::row_major> fah, fal;
                wmma::load_matrix_sync(fah, Ah + (wm*64 + i*16)*PT + ks, PT);
                wmma::load_matrix_sync(fal, Al + (wm*64 + i*16)*PT + ks, PT);
                #pragma unroll
                for (int j = 0; j < 2; j++) {
                    wmma::mma_sync(acc[i][j], fah, fbh[j], acc[i][j]);
                    wmma::mma_sync(acc[i][j], fah, fbl[j], acc[i][j]);
                    wmma::mma_sync(acc[i][j], fal, fbh[j], acc[i][j]);
                }
            }
        }
        __syncthreads();
    }

    // epilogue: stage 16x16 per warp, then float4 (STG.128) global stores
    float* ws = (float*)sm + w * (16*24);
    #pragma unroll
    for (int i = 0; i < 4; i++) {
        #pragma unroll
        for (int j = 0; j < 2; j++) {
            wmma::store_matrix_sync(ws, acc[i][j], 24, wmma::mem_row_major);
            __syncwarp();
            #pragma unroll
            for (int tt = 0; tt < 2; tt++) {
                int idx = lid + tt*32;              // 0..63
                int r = idx >> 2, c4 = (idx & 3) << 2;
                float4 v = *(float4*)(&ws[r*24 + c4]);
                v.x *= SCALE; v.y *= SCALE; v.z *= SCALE; v.w *= SCALE;
                int m = bm + wm*64 + i*16 + r;
                int n = bn + wn*32 + j*16 + c4;
                *(float4*)(&attn[((size_t)bh*L_ + m)*L_ + n]) = v;
            }
            __syncwarp();
        }
    }
}

// ============================================================================
// Softmax: normalizes in place (fp32, streaming stores) + fp16 copy for PV
// ============================================================================
__global__ __launch_bounds__(256) void softmax_kernel(float* __restrict__ attn,
                                                      hf* __restrict__ attn16)
{
    float4* p = (float4*)(attn + (size_t)blockIdx.x * L_);
    hf* p16 = attn16 + (size_t)blockIdx.x * L_;
    const int t = threadIdx.x;
    float4 a = p[t], b = p[t + 256];
    float m = fmaxf(fmaxf(fmaxf(a.x,a.y),fmaxf(a.z,a.w)),
                    fmaxf(fmaxf(b.x,b.y),fmaxf(b.z,b.w)));
    #pragma unroll
    for (int o = 16; o; o >>= 1) m = fmaxf(m, __shfl_xor_sync(0xffffffffu, m, o));
    __shared__ float redm[8], reds[8];
    if ((t & 31) == 0) redm[t >> 5] = m;
    __syncthreads();
    float bm = redm[0];
    #pragma unroll
    for (int q = 1; q < 8; q++) bm = fmaxf(bm, redm[q]);
    a.x = __expf(a.x - bm); a.y = __expf(a.y - bm);
    a.z = __expf(a.z - bm); a.w = __expf(a.w - bm);
    b.x = __expf(b.x - bm); b.y = __expf(b.y - bm);
    b.z = __expf(b.z - bm); b.w = __expf(b.w - bm);
    float s = a.x + a.y + a.z + a.w + b.x + b.y + b.z + b.w;
    #pragma unroll
    for (int o = 16; o; o >>= 1) s += __shfl_xor_sync(0xffffffffu, s, o);
    if ((t & 31) == 0) reds[t >> 5] = s;
    __syncthreads();
    float bs = 0.f;
    #pragma unroll
    for (int q = 0; q < 8; q++) bs += reds[q];
    float inv = 1.0f / bs;
    a.x *= inv; a.y *= inv; a.z *= inv; a.w *= inv;
    b.x *= inv; b.y *= inv; b.z *= inv; b.w *= inv;
    __stwt(&p[t], a);
    __stwt(&p[t + 256], b);
    __half2 h0 = __floats2half2_rn(a.x, a.y);
    __half2 h1 = __floats2half2_rn(a.z, a.w);
    __half2 h2 = __floats2half2_rn(b.x, b.y);
    __half2 h3 = __floats2half2_rn(b.z, b.w);
    uint2 u0; u0.x = *(uint32_t*)&h0; u0.y = *(uint32_t*)&h1;
    uint2 u1; u1.x = *(uint32_t*)&h2; u1.y = *(uint32_t*)&h3;
    *(uint2*)(p16 + t*4)         = u0;
    *(uint2*)(p16 + (t + 256)*4) = u1;
}

// ============================================================================
// PV: O[128x64] = attn16[128x2048] @ V[2048x64], all-fp16 async pipeline.
// ============================================================================
__global__ __launch_bounds__(256, 2) void pv_mma()
{
    extern __shared__ char sm[];
    hf* Ph0 = (hf*)sm;               // [128][PT]
    hf* Ph1 = Ph0 + 128*PT;
    hf* Vh0 = Ph1 + 128*PT;          // [32][PV]
    hf* Vh1 = Vh0 + 32*PV;
    const int tid = threadIdx.x, w = tid >> 5, lid = tid & 31;
    const int wm = w >> 1, wn = w & 1;            // 4 x 2
    const int bh = blockIdx.y, bm = blockIdx.x * 128;
    const hf* A16 = g_attnh + (size_t)bh * L_ * L_;
    const hf* Vg = g_V + (size_t)bh * L_ * DH_;

    wmma::fragment<wmma::accumulator, 16, 16, 16, float> acc[2][2];
    #pragma unroll
    for (int i = 0; i < 2; i++)
        #pragma unroll
        for (int j = 0; j < 2; j++)
            wmma::fill_fragment(acc[i][j], 0.0f);

    async_b(tid, A16, L_, bm, 0, Ph0);
    async_v(tid, Vg, 0, Vh0);
    __pipeline_commit();

    for (int t = 0; t < 64; t++) {
        hf* Pc = (t & 1) ? Ph1 : Ph0;
        hf* Vc = (t & 1) ? Vh1 : Vh0;
        if (t+1 < 64) {
            hf* Pn = (t & 1) ? Ph0 : Ph1;
            hf* Vn = (t & 1) ? Vh0 : Vh1;
            async_b(tid, A16, L_, bm, (t+1)*32, Pn);
            async_v(tid, Vg, (t+1)*32, Vn);
            __pipeline_commit();
        }
        if (t+1 < 64) __pipeline_wait_prior(1);
        else          __pipeline_wait_prior(0);
        __syncthreads();

        #pragma unroll
        for (int ks = 0; ks < 32; ks += 16) {
            wmma::fragment<wmma::matrix_b, 16, 16, 16, hf, wmma::row_major> fbh[2];
            #pragma unroll
            for (int j = 0; j < 2; j++)
                wmma::load_matrix_sync(fbh[j], Vc + ks*PV + wn*32 + j*16, PV);
            #pragma unroll
            for (int i = 0; i < 2; i++) {
                wmma::fragment<wmma::matrix_a, 16, 16, 16, hf, wmma::row_major> fah;
                wmma::load_matrix_sync(fah, Pc + (wm*32 + i*16)*PT + ks, PT);
                #pragma unroll
                for (int j = 0; j < 2; j++)
                    wmma::mma_sync(acc[i][j], fah, fbh[j], acc[i][j]);
            }
        }
        __syncthreads();
    }

    float* ws = (float*)sm + w * (16*24);
    hf* SO = (hf*)(sm + 12288);     // [128][72] fp16
    #pragma unroll
    for (int i = 0; i < 2; i++) {
        #pragma unroll
        for (int j = 0; j < 2; j++) {
            wmma::store_matrix_sync(ws, acc[i][j], 24, wmma::mem_row_major);
            __syncwarp();
            #pragma unroll
            for (int tt = 0; tt < 8; tt++) {
                int e = lid + tt*32, r = e >> 4, c = e & 15;
                int row = wm*32 + i*16 + r;
                int col = wn*32 + j*16 + c;
                SO[row*72 + col] = __float2half_rn(ws[r*24 + c]);
            }
            __syncwarp();
        }
    }
    __syncthreads();
    const int b = bh >> 4, h = bh & 15;
    #pragma unroll
    for (int q = 0; q < 4; q++) {
        int e = tid + q*256;
        int rr = e >> 3, o = e & 7;
        *(uint4*)(&g_Oh[((size_t)(b*L_ + bm + rr))*D_ + h*DH_ + o*8]) =
            *(uint4*)(&SO[rr*72 + o*8]);
    }
}

// ============================================================================
// Output projection: out = g_Oh(fp16) @ Wo + bo, fp32 flat out, fully async
// ============================================================================
__global__ __launch_bounds__(256, 2) void out_proj(
    const hf* __restrict__ Wth, const float* __restrict__ bias,
    float* __restrict__ outF)
{
    extern __shared__ char sm[];
    const int BT = 128*PT;
    hf* Ah0 = (hf*)sm;
    hf* Ah1 = Ah0 + BT;
    hf* Bh0 = Ah1 + BT;
    hf* Bh1 = Bh0 + BT;
    const int tid = threadIdx.x, w = tid >> 5, lid = tid & 31;
    const int wm = w >> 2, wn = w & 3;
    const int bm = blockIdx.y * 128, bn = blockIdx.x * 128;

    wmma::fragment<wmma::accumulator, 16, 16, 16, float> acc[4][2];
    #pragma unroll
    for (int i = 0; i < 4; i++)
        #pragma unroll
        for (int j = 0; j < 2; j++)
            wmma::fill_fragment(acc[i][j], 0.0f);

    async_b(tid, g_Oh, D_, bm, 0, Ah0);
    async_b(tid, Wth, D_, bn, 0, Bh0);
    __pipeline_commit();

    for (int t = 0; t < 32; t++) {
        hf* Ac = (t & 1) ? Ah1 : Ah0;
        hf* Bc = (t & 1) ? Bh1 : Bh0;
        if (t+1 < 32) {
            hf* An = (t & 1) ? Ah0 : Ah1;
            hf* Bn = (t & 1) ? Bh0 : Bh1;
            async_b(tid, g_Oh, D_, bm, (t+1)*32, An);
            async_b(tid, Wth, D_, bn, (t+1)*32, Bn);
            __pipeline_commit();
        }
        if (t+1 < 32) __pipeline_wait_prior(1);
        else          __pipeline_wait_prior(0);
        __syncthreads();

        #pragma unroll
        for (int ks = 0; ks < 32; ks += 16) {
            wmma::fragment<wmma::matrix_b, 16, 16, 16, hf, wmma::col_major> fbh[2];
            #pragma unroll
            for (int j = 0; j < 2; j++)
                wmma::load_matrix_sync(fbh[j], Bc + (wn*32 + j*16)*PT + ks, PT);
            #pragma unroll
            for (int i = 0; i < 4; i++) {
                wmma::fragment<wmma::matrix_a, 16, 16, 16, hf, wmma::row_major> fah;
                wmma::load_matrix_sync(fah, Ac + (wm*64 + i*16)*PT + ks, PT);
                #pragma unroll
                for (int j = 0; j < 2; j++)
                    wmma::mma_sync(acc[i][j], fah, fbh[j], acc[i][j]);
            }
        }
        __syncthreads();
    }

    float* ws = (float*)sm + w * (16*24);
    float* SF = (float*)(sm + 12288);
    #pragma unroll
    for (int i = 0; i < 4; i++) {
        #pragma unroll
        for (int j = 0; j < 2; j++) {
            wmma::store_matrix_sync(ws, acc[i][j], 24, wmma::mem_row_major);
            __syncwarp();
            #pragma unroll
            for (int tt = 0; tt < 8; tt++) {
                int e = lid + tt*32, r = e >> 4, c = e & 15;
                int row = wm*64 + i*16 + r;
                int col = wn*32 + j*16 + c;
                SF[row*132 + col] = ws[r*24 + c] + bias[bn + col];
            }
            __syncwarp();
        }
    }
    __syncthreads();
    #pragma unroll
    for (int q = 0; q < 16; q++) {
        int e = tid + q*256;
        int rr = e >> 5, o = e & 31;
        *(float4*)(outF + (size_t)(bm+rr)*D_ + bn + o*4) = *(float4*)(&SF[rr*132 + o*4]);
    }
}

// ============================================================================
extern "C" void kernel_launch(void* const* d_in, const int* in_sizes, int n_in,
                              void* d_out, int out_size)
{
    const float* q  = (const float*)d_in[0];
    const float* k  = (const float*)d_in[1];
    const float* v  = (const float*)d_in[2];
    const float* Wq = (const float*)d_in[3];
    const float* bq = (const float*)d_in[4];
    const float* Wk = (const float*)d_in[5];
    const float* bk = (const float*)d_in[6];
    const float* Wv = (const float*)d_in[7];
    const float* bv = (const float*)d_in[8];
    const float* Wo = (const float*)d_in[9];
    const float* bo = (const float*)d_in[10];
    float* out = (float*)d_out;

    float *pAttnFb;
    hf *pQh,*pQl,*pKh,*pKl,*pV,*pWth,*pWtl,*pAttn16;
    cudaGetSymbolAddress((void**)&pAttnFb, g_attn_fallback);
    cudaGetSymbolAddress((void**)&pQh, g_Qh);
    cudaGetSymbolAddress((void**)&pQl, g_Ql);
    cudaGetSymbolAddress((void**)&pKh, g_Kh);
    cudaGetSymbolAddress((void**)&pKl, g_Kl);
    cudaGetSymbolAddress((void**)&pV,  g_V);
    cudaGetSymbolAddress((void**)&pWth, g_Wth);
    cudaGetSymbolAddress((void**)&pWtl, g_Wtl);
    cudaGetSymbolAddress((void**)&pAttn16, g_attnh);

    const long long need = (long long)M_ * D_ + (long long)BH_ * L_ * L_;
    float* attn = ((long long)out_size >= need) ? (out + (size_t)M_ * D_) : pAttnFb;

    const int SM_QK     = 81920;
    const int SM_V      = 47104;
    const int SM_SCORES = 40960;
    const int SM_PV     = 30720;
    const int SM_OUT    = 79872;

    cudaFuncSetAttribute(proj_qk,    cudaFuncAttributeMaxDynamicSharedMemorySize, SM_QK);
    cudaFuncSetAttribute(proj_v,     cudaFuncAttributeMaxDynamicSharedMemorySize, SM_V);
    cudaFuncSetAttribute(scores_mma, cudaFuncAttributeMaxDynamicSharedMemorySize, SM_SCORES);
    cudaFuncSetAttribute(pv_mma,     cudaFuncAttributeMaxDynamicSharedMemorySize, SM_PV);
    cudaFuncSetAttribute(out_proj,   cudaFuncAttributeMaxDynamicSharedMemorySize, SM_OUT);

    const size_t WSZ = (size_t)D_ * D_;
    dim3 gW(D_/32, D_/32, 4);
    split_w4_kernel<<<gW, 256>>>(Wq, Wk, Wv, Wo, pWth, pWtl);

    dim3 gQK(D_/128, M_/128, 2);  // (8, 64, 2)
    proj_qk<<<gQK, 256, SM_QK>>>(q, k, pWth + 0*WSZ, pWtl + 0*WSZ,
                                 pWth + 1*WSZ, pWtl + 1*WSZ,
                                 bq, bk, pQh, pQl, pKh, pKl);

    dim3 gProj(D_/128, M_/128);   // (8, 64)
    proj_v<<<gProj, 256, SM_V>>>(v, pWth + 2*WSZ, bv, pV);

    dim3 gS(L_/128, L_/128, BH_); // (16,16,64)
    scores_mma<<<gS, 256, SM_SCORES>>>(attn);

    softmax_kernel<<<BH_*L_, 256>>>(attn, pAttn16);

    dim3 gPV(L_/128, BH_);        // (16, 64)
    pv_mma<<<gPV, 256, SM_PV>>>();

    out_proj<<<gProj, 256, SM_OUT>>>(pWth + 3*WSZ, bo, out);
}

// round 15
// speedup vs baseline: 1.0363x; 1.0363x over previous
#include <cuda_runtime.h>
#include <cuda_fp16.h>
#include <cuda_pipeline.h>
#include <mma.h>
#include <stdint.h>

using namespace nvcuda;

#define B_  4
#define L_  2048
#define D_  1024
#define H_  16
#define DH_ 64
#define M_  (B_*L_)
#define BH_ (B_*H_)
#define SCALE 0.5f
#define PT 40      // fp16 tile pitch (halves): 80B = conflict-free LDSM
#define PV 72      // V tile pitch (halves): 144B = conflict-free LDSM

typedef __half hf;

// ---------------- static scratch ----------------
__device__ hf g_Oh[(size_t)M_*D_];
__device__ hf g_Qh[(size_t)BH_*L_*DH_];
__device__ hf g_Ql[(size_t)BH_*L_*DH_];
__device__ hf g_Kh[(size_t)BH_*L_*DH_];
__device__ hf g_Kl[(size_t)BH_*L_*DH_];
__device__ hf g_V [(size_t)BH_*L_*DH_];
__device__ hf g_attnh[(size_t)BH_*L_*L_];
__device__ hf g_Wth[4][(size_t)D_*D_];
__device__ hf g_Wtl[4][(size_t)D_*D_];
__device__ float g_attn_fallback[(size_t)BH_*L_*L_];

__device__ __forceinline__ void split1h(float x, unsigned short& h, unsigned short& l){
    hf hb = __float2half_rn(x);
    float r = x - __half2float(hb);
    hf lb = __float2half_rn(r);
    h = __half_as_ushort(hb);
    l = __half_as_ushort(lb);
}

// ---- register-prefetch A tile: fp32 [128 x 32] ----
struct ARegs { float4 v[4]; };

__device__ __forceinline__ void fetch_a(ARegs& r, const float* __restrict__ X, int ldx,
                                        int row0, int k0, int tid){
    #pragma unroll
    for (int i = 0; i < 4; i++) {
        int e = tid + i*256;
        int m = e >> 3, k4 = (e & 7) << 2;
        r.v[i] = *(const float4*)(X + (size_t)(row0+m)*ldx + k0 + k4);
    }
}
__device__ __forceinline__ void store_a_split(const ARegs& r, hf* dh, hf* dl, int tid){
    #pragma unroll
    for (int i = 0; i < 4; i++) {
        int e = tid + i*256;
        int m = e >> 3, k4 = (e & 7) << 2;
        unsigned short h0,h1,h2,h3,l0,l1,l2,l3;
        split1h(r.v[i].x,h0,l0); split1h(r.v[i].y,h1,l1);
        split1h(r.v[i].z,h2,l2); split1h(r.v[i].w,h3,l3);
        uint2 hp = make_uint2((uint32_t)h0 | ((uint32_t)h1<<16), (uint32_t)h2 | ((uint32_t)h3<<16));
        uint2 lp = make_uint2((uint32_t)l0 | ((uint32_t)l1<<16), (uint32_t)l2 | ((uint32_t)l3<<16));
        *(uint2*)(dh + m*PT + k4) = hp;
        *(uint2*)(dl + m*PT + k4) = lp;
    }
}
__device__ __forceinline__ void store_a_round(const ARegs& r, hf* d, int tid){
    #pragma unroll
    for (int i = 0; i < 4; i++) {
        int e = tid + i*256;
        int m = e >> 3, k4 = (e & 7) << 2;
        __half2 p0 = __floats2half2_rn(r.v[i].x, r.v[i].y);
        __half2 p1 = __floats2half2_rn(r.v[i].z, r.v[i].w);
        uint2 u;
        u.x = *(uint32_t*)&p0;
        u.y = *(uint32_t*)&p1;
        *(uint2*)(d + m*PT + k4) = u;
    }
}

// async copy fp16 [128 x 32] tile (pitch PT)
__device__ __forceinline__ void async_b(int tid, const hf* __restrict__ G, int ld,
                                        int row0, int k0, hf* dst){
    #pragma unroll
    for (int i = 0; i < 2; i++) {
        int e = tid + i*256;
        int rr = e >> 2, o = e & 3;
        __pipeline_memcpy_async(dst + rr*PT + o*8,
                                G + (size_t)(row0+rr)*ld + k0 + o*8, 16);
    }
}
// async copy fp16 [32 x 64] V tile (pitch PV)
__device__ __forceinline__ void async_v(int tid, const hf* __restrict__ G,
                                        int k0, hf* dst){
    int rr = tid >> 3, o = tid & 7;
    __pipeline_memcpy_async(dst + rr*PV + o*8,
                            G + (size_t)(k0+rr)*DH_ + o*8, 16);
}

// ============================================================================
// Weight split+transpose: all 4 weights in one launch
// ============================================================================
__global__ __launch_bounds__(256) void split_w4_kernel(
    const float* __restrict__ W0, const float* __restrict__ W1,
    const float* __restrict__ W2, const float* __restrict__ W3,
    hf* __restrict__ ohBase, hf* __restrict__ olBase)
{
    const int z = blockIdx.z;
    const float* W = (z == 0) ? W0 : (z == 1) ? W1 : (z == 2) ? W2 : W3;
    hf* oh = ohBase + (size_t)z * D_ * D_;
    hf* ol = olBase + (size_t)z * D_ * D_;
    __shared__ float s[32][33];
    const int bk = blockIdx.x*32, bn = blockIdx.y*32;
    const int tx = threadIdx.x & 31, ty = threadIdx.x >> 5;
    #pragma unroll
    for (int i = 0; i < 4; i++)
        s[ty + i*8][tx] = W[(size_t)(bk + ty + i*8)*D_ + bn + tx];
    __syncthreads();
    #pragma unroll
    for (int i = 0; i < 4; i++) {
        float v = s[tx][ty + i*8];
        unsigned short h, l; split1h(v, h, l);
        size_t a = (size_t)(bn + ty + i*8)*D_ + bk + tx;
        oh[a] = __ushort_as_half(h);
        ol[a] = __ushort_as_half(l);
    }
}

// ============================================================================
// Q+K projections fused (3-term fp16, hi/lo out), A smem double-buffered
// ============================================================================
__global__ __launch_bounds__(256, 2) void proj_qk(
    const float* __restrict__ qin, const float* __restrict__ kin,
    const hf* __restrict__ Wth0, const hf* __restrict__ Wtl0,
    const hf* __restrict__ Wth1, const hf* __restrict__ Wtl1,
    const float* __restrict__ bq, const float* __restrict__ bk,
    hf* __restrict__ Qh, hf* __restrict__ Ql,
    hf* __restrict__ Kh, hf* __restrict__ Kl)
{
    const int z = blockIdx.z;
    const float* X   = z ? kin  : qin;
    const hf* Wth    = z ? Wth1 : Wth0;
    const hf* Wtl    = z ? Wtl1 : Wtl0;
    const float* bias= z ? bk   : bq;
    hf* outH         = z ? Kh   : Qh;
    hf* outL         = z ? Kl   : Ql;

    extern __shared__ char sm[];
    const int BT = 128*PT;
    hf* Ah0 = (hf*)sm;             // A double-buffered: 4 tiles
    hf* Al0 = Ah0 + BT;
    hf* Ah1 = Al0 + BT;
    hf* Al1 = Ah1 + BT;
    hf* Bh0 = Al1 + BT;            // B double-buffered: 4 tiles
    hf* Bl0 = Bh0 + BT;
    hf* Bh1 = Bl0 + BT;
    hf* Bl1 = Bh1 + BT;
    const int tid = threadIdx.x, w = tid >> 5, lid = tid & 31;
    const int wm = w >> 2, wn = w & 3;
    const int bm = blockIdx.y * 128, bn = blockIdx.x * 128;

    wmma::fragment<wmma::accumulator, 16, 16, 16, float> acc[4][2];
    #pragma unroll
    for (int i = 0; i < 4; i++)
        #pragma unroll
        for (int j = 0; j < 2; j++)
            wmma::fill_fragment(acc[i][j], 0.0f);

    async_b(tid, Wth, D_, bn, 0, Bh0);
    async_b(tid, Wtl, D_, bn, 0, Bl0);
    __pipeline_commit();
    ARegs ra;
    fetch_a(ra, X, D_, bm, 0, tid);
    store_a_split(ra, Ah0, Al0, tid);   // stage A tile 0
    __pipeline_wait_prior(0);
    __syncthreads();
    fetch_a(ra, X, D_, bm, 32, tid);

    for (int t = 0; t < 32; t++) {
        hf* Ahc = (t & 1) ? Ah1 : Ah0;
        hf* Alc = (t & 1) ? Al1 : Al0;
        hf* Bhc = (t & 1) ? Bh1 : Bh0;
        hf* Blc = (t & 1) ? Bl1 : Bl0;
        if (t+1 < 32) {
            hf* Bhn = (t & 1) ? Bh0 : Bh1;
            hf* Bln = (t & 1) ? Bl0 : Bl1;
            async_b(tid, Wth, D_, bn, (t+1)*32, Bhn);
            async_b(tid, Wtl, D_, bn, (t+1)*32, Bln);
            __pipeline_commit();
            // split+store NEXT A tile into the other buffer (overlaps this t's MMAs)
            hf* Ahn = (t & 1) ? Ah0 : Ah1;
            hf* Aln = (t & 1) ? Al0 : Al1;
            store_a_split(ra, Ahn, Aln, tid);
        }

        #pragma unroll
        for (int ks = 0; ks < 32; ks += 16) {
            wmma::fragment<wmma::matrix_b, 16, 16, 16, hf, wmma::col_major> fbh[2], fbl[2];
            #pragma unroll
            for (int j = 0; j < 2; j++) {
                wmma::load_matrix_sync(fbh[j], Bhc + (wn*32 + j*16)*PT + ks, PT);
                wmma::load_matrix_sync(fbl[j], Blc + (wn*32 + j*16)*PT + ks, PT);
            }
            #pragma unroll
            for (int i = 0; i < 4; i++) {
                wmma::fragment<wmma::matrix_a, 16, 16, 16, hf, wmma::row_major> fah, fal;
                wmma::load_matrix_sync(fah, Ahc + (wm*64 + i*16)*PT + ks, PT);
                wmma::load_matrix_sync(fal, Alc + (wm*64 + i*16)*PT + ks, PT);
                #pragma unroll
                for (int j = 0; j < 2; j++) {
                    wmma::mma_sync(acc[i][j], fah, fbh[j], acc[i][j]);
                    wmma::mma_sync(acc[i][j], fah, fbl[j], acc[i][j]);
                    wmma::mma_sync(acc[i][j], fal, fbh[j], acc[i][j]);
                }
            }
        }
        if (t+1 < 32) {
            __pipeline_wait_prior(0);
            __syncthreads();
            if (t+2 < 32) fetch_a(ra, X, D_, bm, (t+2)*32, tid);
        }
    }
    __syncthreads();

    float* ws = (float*)sm + w * (16*24);
    hf* SH = (hf*)(sm + 12288);
    hf* SL = (hf*)(sm + 12288 + 34816);
    #pragma unroll
    for (int i = 0; i < 4; i++) {
        #pragma unroll
        for (int j = 0; j < 2; j++) {
            wmma::store_matrix_sync(ws, acc[i][j], 24, wmma::mem_row_major);
            __syncwarp();
            #pragma unroll
            for (int tt = 0; tt < 8; tt++) {
                int e = lid + tt*32, r = e >> 4, c = e & 15;
                int row = wm*64 + i*16 + r;
                int col = wn*32 + j*16 + c;
                float v = ws[r*24 + c] + bias[bn + col];
                unsigned short hs, ls; split1h(v, hs, ls);
                SH[row*136 + col] = __ushort_as_half(hs);
                SL[row*136 + col] = __ushort_as_half(ls);
            }
            __syncwarp();
        }
    }
    __syncthreads();
    #pragma unroll
    for (int q = 0; q < 8; q++) {
        int e = tid + q*256;
        int rr = e >> 4, o = e & 15;
        int m = bm + rr, bb = m >> 11, l = m & (L_-1);
        int n0 = bn + o*8, h = n0 >> 6, dh = n0 & 63;
        size_t a = (((size_t)(bb*H_ + h))*L_ + l)*DH_ + dh;
        *(uint4*)(outH + a) = *(uint4*)(&SH[rr*136 + o*8]);
        *(uint4*)(outL + a) = *(uint4*)(&SL[rr*136 + o*8]);
    }
}

// ============================================================================
// V projection (1-term, fp16 out), A smem double-buffered
// ============================================================================
__global__ __launch_bounds__(256, 2) void proj_v(
    const float* __restrict__ X,
    const hf* __restrict__ Wth, const float* __restrict__ bias,
    hf* __restrict__ outH)
{
    extern __shared__ char sm[];
    const int BT = 128*PT;
    hf* Ah0 = (hf*)sm;
    hf* Ah1 = Ah0 + BT;
    hf* Bh0 = Ah1 + BT;
    hf* Bh1 = Bh0 + BT;
    const int tid = threadIdx.x, w = tid >> 5, lid = tid & 31;
    const int wm = w >> 2, wn = w & 3;
    const int bm = blockIdx.y * 128, bn = blockIdx.x * 128;

    wmma::fragment<wmma::accumulator, 16, 16, 16, float> acc[4][2];
    #pragma unroll
    for (int i = 0; i < 4; i++)
        #pragma unroll
        for (int j = 0; j < 2; j++)
            wmma::fill_fragment(acc[i][j], 0.0f);

    async_b(tid, Wth, D_, bn, 0, Bh0);
    __pipeline_commit();
    ARegs ra;
    fetch_a(ra, X, D_, bm, 0, tid);
    store_a_round(ra, Ah0, tid);
    __pipeline_wait_prior(0);
    __syncthreads();
    fetch_a(ra, X, D_, bm, 32, tid);

    for (int t = 0; t < 32; t++) {
        hf* Ahc = (t & 1) ? Ah1 : Ah0;
        hf* Bhc = (t & 1) ? Bh1 : Bh0;
        if (t+1 < 32) {
            hf* Bhn = (t & 1) ? Bh0 : Bh1;
            async_b(tid, Wth, D_, bn, (t+1)*32, Bhn);
            __pipeline_commit();
            hf* Ahn = (t & 1) ? Ah0 : Ah1;
            store_a_round(ra, Ahn, tid);
        }

        #pragma unroll
        for (int ks = 0; ks < 32; ks += 16) {
            wmma::fragment<wmma::matrix_b, 16, 16, 16, hf, wmma::col_major> fbh[2];
            #pragma unroll
            for (int j = 0; j < 2; j++)
                wmma::load_matrix_sync(fbh[j], Bhc + (wn*32 + j*16)*PT + ks, PT);
            #pragma unroll
            for (int i = 0; i < 4; i++) {
                wmma::fragment<wmma::matrix_a, 16, 16, 16, hf, wmma::row_major> fah;
                wmma::load_matrix_sync(fah, Ahc + (wm*64 + i*16)*PT + ks, PT);
                #pragma unroll
                for (int j = 0; j < 2; j++)
                    wmma::mma_sync(acc[i][j], fah, fbh[j], acc[i][j]);
            }
        }
        if (t+1 < 32) {
            __pipeline_wait_prior(0);
            __syncthreads();
            if (t+2 < 32) fetch_a(ra, X, D_, bm, (t+2)*32, tid);
        }
    }
    __syncthreads();

    float* ws = (float*)sm + w * (16*24);
    hf* SH = (hf*)(sm + 12288);
    #pragma unroll
    for (int i = 0; i < 4; i++) {
        #pragma unroll
        for (int j = 0; j < 2; j++) {
            wmma::store_matrix_sync(ws, acc[i][j], 24, wmma::mem_row_major);
            __syncwarp();
            #pragma unroll
            for (int tt = 0; tt < 8; tt++) {
                int e = lid + tt*32, r = e >> 4, c = e & 15;
                int row = wm*64 + i*16 + r;
                int col = wn*32 + j*16 + c;
                SH[row*136 + col] = __float2half_rn(ws[r*24 + c] + bias[bn + col]);
            }
            __syncwarp();
        }
    }
    __syncthreads();
    #pragma unroll
    for (int q = 0; q < 8; q++) {
        int e = tid + q*256;
        int rr = e >> 4, o = e & 15;
        int m = bm + rr, bb = m >> 11, l = m & (L_-1);
        int n0 = bn + o*8, h = n0 >> 6, dh = n0 & 63;
        size_t a = (((size_t)(bb*H_ + h))*L_ + l)*DH_ + dh;
        *(uint4*)(outH + a) = *(uint4*)(&SH[rr*136 + o*8]);
    }
}

// ============================================================================
// Scores: 3-term fp16, cp.async tile staging, float4 epilogue
// ============================================================================
__global__ __launch_bounds__(256, 2) void scores_mma(float* __restrict__ attn)
{
    extern __shared__ char sm[];
    hf* Ah = (hf*)sm;
    hf* Al = Ah + 128*PT;
    hf* Bh = Al + 128*PT;
    hf* Bl = Bh + 128*PT;
    const int tid = threadIdx.x, w = tid >> 5, lid = tid & 31;
    const int wm = w >> 2, wn = w & 3;
    const int bh = blockIdx.z, bm = blockIdx.y * 128, bn = blockIdx.x * 128;
    const size_t qo = (size_t)bh * L_ * DH_;

    wmma::fragment<wmma::accumulator, 16, 16, 16, float> acc[4][2];
    #pragma unroll
    for (int i = 0; i < 4; i++)
        #pragma unroll
        for (int j = 0; j < 2; j++)
            wmma::fill_fragment(acc[i][j], 0.0f);

    #pragma unroll
    for (int t = 0; t < 2; t++) {
        async_b(tid, g_Qh + qo, DH_, bm, t*32, Ah);
        async_b(tid, g_Ql + qo, DH_, bm, t*32, Al);
        async_b(tid, g_Kh + qo, DH_, bn, t*32, Bh);
        async_b(tid, g_Kl + qo, DH_, bn, t*32, Bl);
        __pipeline_commit();
        __pipeline_wait_prior(0);
        __syncthreads();
        #pragma unroll
        for (int ks = 0; ks < 32; ks += 16) {
            wmma::fragment<wmma::matrix_b, 16, 16, 16, hf, wmma::col_major> fbh[2], fbl[2];
            #pragma unroll
            for (int j = 0; j < 2; j++) {
                wmma::load_matrix_sync(fbh[j], Bh + (wn*32 + j*16)*PT + ks, PT);
                wmma::load_matrix_sync(fbl[j], Bl + (wn*32 + j*16)*PT + ks, PT);
            }
            #pragma unroll
            for (int i = 0; i < 4; i++) {
                wmma::fragment<wmma::matrix_a, 16, 16, 16, hf, wmma::row_major> fah, fal;
                wmma::load_matrix_sync(fah, Ah + (wm*64 + i*16)*PT + ks, PT);
                wmma::load_matrix_sync(fal, Al + (wm*64 + i*16)*PT + ks, PT);
                #pragma unroll
                for (int j = 0; j < 2; j++) {
                    wmma::mma_sync(acc[i][j], fah, fbh[j], acc[i][j]);
                    wmma::mma_sync(acc[i][j], fah, fbl[j], acc[i][j]);
                    wmma::mma_sync(acc[i][j], fal, fbh[j], acc[i][j]);
                }
            }
        }
        __syncthreads();
    }

    float* ws = (float*)sm + w * (16*24);
    #pragma unroll
    for (int i = 0; i < 4; i++) {
        #pragma unroll
        for (int j = 0; j < 2; j++) {
            wmma::store_matrix_sync(ws, acc[i][j], 24, wmma::mem_row_major);
            __syncwarp();
            #pragma unroll
            for (int tt = 0; tt < 2; tt++) {
                int idx = lid + tt*32;
                int r = idx >> 2, c4 = (idx & 3) << 2;
                float4 v = *(float4*)(&ws[r*24 + c4]);
                v.x *= SCALE; v.y *= SCALE; v.z *= SCALE; v.w *= SCALE;
                int m = bm + wm*64 + i*16 + r;
                int n = bn + wn*32 + j*16 + c4;
                *(float4*)(&attn[((size_t)bh*L_ + m)*L_ + n]) = v;
            }
            __syncwarp();
        }
    }
}

// ============================================================================
// Softmax: fp32 in-place (streaming) + fp16 copy for PV
// ============================================================================
__global__ __launch_bounds__(256) void softmax_kernel(float* __restrict__ attn,
                                                      hf* __restrict__ attn16)
{
    float4* p = (float4*)(attn + (size_t)blockIdx.x * L_);
    hf* p16 = attn16 + (size_t)blockIdx.x * L_;
    const int t = threadIdx.x;
    float4 a = p[t], b = p[t + 256];
    float m = fmaxf(fmaxf(fmaxf(a.x,a.y),fmaxf(a.z,a.w)),
                    fmaxf(fmaxf(b.x,b.y),fmaxf(b.z,b.w)));
    #pragma unroll
    for (int o = 16; o; o >>= 1) m = fmaxf(m, __shfl_xor_sync(0xffffffffu, m, o));
    __shared__ float redm[8], reds[8];
    if ((t & 31) == 0) redm[t >> 5] = m;
    __syncthreads();
    float bm = redm[0];
    #pragma unroll
    for (int q = 1; q < 8; q++) bm = fmaxf(bm, redm[q]);
    a.x = __expf(a.x - bm); a.y = __expf(a.y - bm);
    a.z = __expf(a.z - bm); a.w = __expf(a.w - bm);
    b.x = __expf(b.x - bm); b.y = __expf(b.y - bm);
    b.z = __expf(b.z - bm); b.w = __expf(b.w - bm);
    float s = a.x + a.y + a.z + a.w + b.x + b.y + b.z + b.w;
    #pragma unroll
    for (int o = 16; o; o >>= 1) s += __shfl_xor_sync(0xffffffffu, s, o);
    if ((t & 31) == 0) reds[t >> 5] = s;
    __syncthreads();
    float bs = 0.f;
    #pragma unroll
    for (int q = 0; q < 8; q++) bs += reds[q];
    float inv = 1.0f / bs;
    a.x *= inv; a.y *= inv; a.z *= inv; a.w *= inv;
    b.x *= inv; b.y *= inv; b.z *= inv; b.w *= inv;
    __stwt(&p[t], a);
    __stwt(&p[t + 256], b);
    __half2 h0 = __floats2half2_rn(a.x, a.y);
    __half2 h1 = __floats2half2_rn(a.z, a.w);
    __half2 h2 = __floats2half2_rn(b.x, b.y);
    __half2 h3 = __floats2half2_rn(b.z, b.w);
    uint2 u0; u0.x = *(uint32_t*)&h0; u0.y = *(uint32_t*)&h1;
    uint2 u1; u1.x = *(uint32_t*)&h2; u1.y = *(uint32_t*)&h3;
    *(uint2*)(p16 + t*4)         = u0;
    *(uint2*)(p16 + (t + 256)*4) = u1;
}

// ============================================================================
// PV: all-fp16 async pipeline
// ============================================================================
__global__ __launch_bounds__(256, 2) void pv_mma()
{
    extern __shared__ char sm[];
    hf* Ph0 = (hf*)sm;
    hf* Ph1 = Ph0 + 128*PT;
    hf* Vh0 = Ph1 + 128*PT;
    hf* Vh1 = Vh0 + 32*PV;
    const int tid = threadIdx.x, w = tid >> 5, lid = tid & 31;
    const int wm = w >> 1, wn = w & 1;
    const int bh = blockIdx.y, bm = blockIdx.x * 128;
    const hf* A16 = g_attnh + (size_t)bh * L_ * L_;
    const hf* Vg = g_V + (size_t)bh * L_ * DH_;

    wmma::fragment<wmma::accumulator, 16, 16, 16, float> acc[2][2];
    #pragma unroll
    for (int i = 0; i < 2; i++)
        #pragma unroll
        for (int j = 0; j < 2; j++)
            wmma::fill_fragment(acc[i][j], 0.0f);

    async_b(tid, A16, L_, bm, 0, Ph0);
    async_v(tid, Vg, 0, Vh0);
    __pipeline_commit();

    for (int t = 0; t < 64; t++) {
        hf* Pc = (t & 1) ? Ph1 : Ph0;
        hf* Vc = (t & 1) ? Vh1 : Vh0;
        if (t+1 < 64) {
            hf* Pn = (t & 1) ? Ph0 : Ph1;
            hf* Vn = (t & 1) ? Vh0 : Vh1;
            async_b(tid, A16, L_, bm, (t+1)*32, Pn);
            async_v(tid, Vg, (t+1)*32, Vn);
            __pipeline_commit();
        }
        if (t+1 < 64) __pipeline_wait_prior(1);
        else          __pipeline_wait_prior(0);
        __syncthreads();

        #pragma unroll
        for (int ks = 0; ks < 32; ks += 16) {
            wmma::fragment<wmma::matrix_b, 16, 16, 16, hf, wmma::row_major> fbh[2];
            #pragma unroll
            for (int j = 0; j < 2; j++)
                wmma::load_matrix_sync(fbh[j], Vc + ks*PV + wn*32 + j*16, PV);
            #pragma unroll
            for (int i = 0; i < 2; i++) {
                wmma::fragment<wmma::matrix_a, 16, 16, 16, hf, wmma::row_major> fah;
                wmma::load_matrix_sync(fah, Pc + (wm*32 + i*16)*PT + ks, PT);
                #pragma unroll
                for (int j = 0; j < 2; j++)
                    wmma::mma_sync(acc[i][j], fah, fbh[j], acc[i][j]);
            }
        }
        __syncthreads();
    }

    float* ws = (float*)sm + w * (16*24);
    hf* SO = (hf*)(sm + 12288);
    #pragma unroll
    for (int i = 0; i < 2; i++) {
        #pragma unroll
        for (int j = 0; j < 2; j++) {
            wmma::store_matrix_sync(ws, acc[i][j], 24, wmma::mem_row_major);
            __syncwarp();
            #pragma unroll
            for (int tt = 0; tt < 8; tt++) {
                int e = lid + tt*32, r = e >> 4, c = e & 15;
                int row = wm*32 + i*16 + r;
                int col = wn*32 + j*16 + c;
                SO[row*72 + col] = __float2half_rn(ws[r*24 + c]);
            }
            __syncwarp();
        }
    }
    __syncthreads();
    const int b = bh >> 4, h = bh & 15;
    #pragma unroll
    for (int q = 0; q < 4; q++) {
        int e = tid + q*256;
        int rr = e >> 3, o = e & 7;
        *(uint4*)(&g_Oh[((size_t)(b*L_ + bm + rr))*D_ + h*DH_ + o*8]) =
            *(uint4*)(&SO[rr*72 + o*8]);
    }
}

// ============================================================================
// Output projection: fully async fp16 A/B
// ============================================================================
__global__ __launch_bounds__(256, 2) void out_proj(
    const hf* __restrict__ Wth, const float* __restrict__ bias,
    float* __restrict__ outF)
{
    extern __shared__ char sm[];
    const int BT = 128*PT;
    hf* Ah0 = (hf*)sm;
    hf* Ah1 = Ah0 + BT;
    hf* Bh0 = Ah1 + BT;
    hf* Bh1 = Bh0 + BT;
    const int tid = threadIdx.x, w = tid >> 5, lid = tid & 31;
    const int wm = w >> 2, wn = w & 3;
    const int bm = blockIdx.y * 128, bn = blockIdx.x * 128;

    wmma::fragment<wmma::accumulator, 16, 16, 16, float> acc[4][2];
    #pragma unroll
    for (int i = 0; i < 4; i++)
        #pragma unroll
        for (int j = 0; j < 2; j++)
            wmma::fill_fragment(acc[i][j], 0.0f);

    async_b(tid, g_Oh, D_, bm, 0, Ah0);
    async_b(tid, Wth, D_, bn, 0, Bh0);
    __pipeline_commit();

    for (int t = 0; t < 32; t++) {
        hf* Ac = (t & 1) ? Ah1 : Ah0;
        hf* Bc = (t & 1) ? Bh1 : Bh0;
        if (t+1 < 32) {
            hf* An = (t & 1) ? Ah0 : Ah1;
            hf* Bn = (t & 1) ? Bh0 : Bh1;
            async_b(tid, g_Oh, D_, bm, (t+1)*32, An);
            async_b(tid, Wth, D_, bn, (t+1)*32, Bn);
            __pipeline_commit();
        }
        if (t+1 < 32) __pipeline_wait_prior(1);
        else          __pipeline_wait_prior(0);
        __syncthreads();

        #pragma unroll
        for (int ks = 0; ks < 32; ks += 16) {
            wmma::fragment<wmma::matrix_b, 16, 16, 16, hf, wmma::col_major> fbh[2];
            #pragma unroll
            for (int j = 0; j < 2; j++)
                wmma::load_matrix_sync(fbh[j], Bc + (wn*32 + j*16)*PT + ks, PT);
            #pragma unroll
            for (int i = 0; i < 4; i++) {
                wmma::fragment<wmma::matrix_a, 16, 16, 16, hf, wmma::row_major> fah;
                wmma::load_matrix_sync(fah, Ac + (wm*64 + i*16)*PT + ks, PT);
                #pragma unroll
                for (int j = 0; j < 2; j++)
                    wmma::mma_sync(acc[i][j], fah, fbh[j], acc[i][j]);
            }
        }
        __syncthreads();
    }

    float* ws = (float*)sm + w * (16*24);
    float* SF = (float*)(sm + 12288);
    #pragma unroll
    for (int i = 0; i < 4; i++) {
        #pragma unroll
        for (int j = 0; j < 2; j++) {
            wmma::store_matrix_sync(ws, acc[i][j], 24, wmma::mem_row_major);
            __syncwarp();
            #pragma unroll
            for (int tt = 0; tt < 8; tt++) {
                int e = lid + tt*32, r = e >> 4, c = e & 15;
                int row = wm*64 + i*16 + r;
                int col = wn*32 + j*16 + c;
                SF[row*132 + col] = ws[r*24 + c] + bias[bn + col];
            }
            __syncwarp();
        }
    }
    __syncthreads();
    #pragma unroll
    for (int q = 0; q < 16; q++) {
        int e = tid + q*256;
        int rr = e >> 5, o = e & 31;
        *(float4*)(outF + (size_t)(bm+rr)*D_ + bn + o*4) = *(float4*)(&SF[rr*132 + o*4]);
    }
}

// ============================================================================
extern "C" void kernel_launch(void* const* d_in, const int* in_sizes, int n_in,
                              void* d_out, int out_size)
{
    const float* q  = (const float*)d_in[0];
    const float* k  = (const float*)d_in[1];
    const float* v  = (const float*)d_in[2];
    const float* Wq = (const float*)d_in[3];
    const float* bq = (const float*)d_in[4];
    const float* Wk = (const float*)d_in[5];
    const float* bk = (const float*)d_in[6];
    const float* Wv = (const float*)d_in[7];
    const float* bv = (const float*)d_in[8];
    const float* Wo = (const float*)d_in[9];
    const float* bo = (const float*)d_in[10];
    float* out = (float*)d_out;

    float *pAttnFb;
    hf *pQh,*pQl,*pKh,*pKl,*pV,*pWth,*pWtl,*pAttn16;
    cudaGetSymbolAddress((void**)&pAttnFb, g_attn_fallback);
    cudaGetSymbolAddress((void**)&pQh, g_Qh);
    cudaGetSymbolAddress((void**)&pQl, g_Ql);
    cudaGetSymbolAddress((void**)&pKh, g_Kh);
    cudaGetSymbolAddress((void**)&pKl, g_Kl);
    cudaGetSymbolAddress((void**)&pV,  g_V);
    cudaGetSymbolAddress((void**)&pWth, g_Wth);
    cudaGetSymbolAddress((void**)&pWtl, g_Wtl);
    cudaGetSymbolAddress((void**)&pAttn16, g_attnh);

    const long long need = (long long)M_ * D_ + (long long)BH_ * L_ * L_;
    float* attn = ((long long)out_size >= need) ? (out + (size_t)M_ * D_) : pAttnFb;

    const int SM_QK     = 81920;   // mainloop 8*10240=81920, epi 81920
    const int SM_V      = 47104;   // mainloop 4*10240=40960, epi 47104
    const int SM_SCORES = 40960;
    const int SM_PV     = 30720;
    const int SM_OUT    = 79872;

    cudaFuncSetAttribute(proj_qk,    cudaFuncAttributeMaxDynamicSharedMemorySize, SM_QK);
    cudaFuncSetAttribute(proj_v,     cudaFuncAttributeMaxDynamicSharedMemorySize, SM_V);
    cudaFuncSetAttribute(scores_mma, cudaFuncAttributeMaxDynamicSharedMemorySize, SM_SCORES);
    cudaFuncSetAttribute(pv_mma,     cudaFuncAttributeMaxDynamicSharedMemorySize, SM_PV);
    cudaFuncSetAttribute(out_proj,   cudaFuncAttributeMaxDynamicSharedMemorySize, SM_OUT);

    const size_t WSZ = (size_t)D_ * D_;
    dim3 gW(D_/32, D_/32, 4);
    split_w4_kernel<<<gW, 256>>>(Wq, Wk, Wv, Wo, pWth, pWtl);

    dim3 gQK(D_/128, M_/128, 2);
    proj_qk<<<gQK, 256, SM_QK>>>(q, k, pWth + 0*WSZ, pWtl + 0*WSZ,
                                 pWth + 1*WSZ, pWtl + 1*WSZ,
                                 bq, bk, pQh, pQl, pKh, pKl);

    dim3 gProj(D_/128, M_/128);
    proj_v<<<gProj, 256, SM_V>>>(v, pWth + 2*WSZ, bv, pV);

    dim3 gS(L_/128, L_/128, BH_);
    scores_mma<<<gS, 256, SM_SCORES>>>(attn);

    softmax_kernel<<<BH_*L_, 256>>>(attn, pAttn16);

    dim3 gPV(L_/128, BH_);
    pv_mma<<<gPV, 256, SM_PV>>>();

    out_proj<<<gProj, 256, SM_OUT>>>(pWth + 3*WSZ, bo, out);
}

// round 16
// speedup vs baseline: 1.0436x; 1.0070x over previous
#include <cuda_runtime.h>
#include <cuda_fp16.h>
#include <cuda_pipeline.h>
#include <mma.h>
#include <stdint.h>

using namespace nvcuda;

#define B_  4
#define L_  2048
#define D_  1024
#define H_  16
#define DH_ 64
#define M_  (B_*L_)
#define BH_ (B_*H_)
#define SCALE 0.5f
#define PT 40      // fp16 tile pitch (halves): 80B = conflict-free LDSM
#define PV 72      // V tile pitch (halves): 144B = conflict-free LDSM

typedef __half hf;

// ---------------- static scratch ----------------
__device__ hf g_Oh[(size_t)M_*D_];
__device__ hf g_Qh[(size_t)BH_*L_*DH_];
__device__ hf g_Ql[(size_t)BH_*L_*DH_];
__device__ hf g_Kh[(size_t)BH_*L_*DH_];
__device__ hf g_Kl[(size_t)BH_*L_*DH_];
__device__ hf g_V [(size_t)BH_*L_*DH_];
__device__ hf g_attnh[(size_t)BH_*L_*L_];
__device__ hf g_Wth[4][(size_t)D_*D_];
__device__ hf g_Wtl[4][(size_t)D_*D_];
__device__ float g_attn_fallback[(size_t)BH_*L_*L_];

__device__ __forceinline__ void split1h(float x, unsigned short& h, unsigned short& l){
    hf hb = __float2half_rn(x);
    float r = x - __half2float(hb);
    hf lb = __float2half_rn(r);
    h = __half_as_ushort(hb);
    l = __half_as_ushort(lb);
}

// ---- register-prefetch A tile: fp32 [128 x 32] ----
struct ARegs { float4 v[4]; };

__device__ __forceinline__ void fetch_a(ARegs& r, const float* __restrict__ X, int ldx,
                                        int row0, int k0, int tid){
    #pragma unroll
    for (int i = 0; i < 4; i++) {
        int e = tid + i*256;
        int m = e >> 3, k4 = (e & 7) << 2;
        r.v[i] = *(const float4*)(X + (size_t)(row0+m)*ldx + k0 + k4);
    }
}
__device__ __forceinline__ void store_a_split(const ARegs& r, hf* dh, hf* dl, int tid){
    #pragma unroll
    for (int i = 0; i < 4; i++) {
        int e = tid + i*256;
        int m = e >> 3, k4 = (e & 7) << 2;
        unsigned short h0,h1,h2,h3,l0,l1,l2,l3;
        split1h(r.v[i].x,h0,l0); split1h(r.v[i].y,h1,l1);
        split1h(r.v[i].z,h2,l2); split1h(r.v[i].w,h3,l3);
        uint2 hp = make_uint2((uint32_t)h0 | ((uint32_t)h1<<16), (uint32_t)h2 | ((uint32_t)h3<<16));
        uint2 lp = make_uint2((uint32_t)l0 | ((uint32_t)l1<<16), (uint32_t)l2 | ((uint32_t)l3<<16));
        *(uint2*)(dh + m*PT + k4) = hp;
        *(uint2*)(dl + m*PT + k4) = lp;
    }
}
__device__ __forceinline__ void store_a_round(const ARegs& r, hf* d, int tid){
    #pragma unroll
    for (int i = 0; i < 4; i++) {
        int e = tid + i*256;
        int m = e >> 3, k4 = (e & 7) << 2;
        __half2 p0 = __floats2half2_rn(r.v[i].x, r.v[i].y);
        __half2 p1 = __floats2half2_rn(r.v[i].z, r.v[i].w);
        uint2 u;
        u.x = *(uint32_t*)&p0;
        u.y = *(uint32_t*)&p1;
        *(uint2*)(d + m*PT + k4) = u;
    }
}

// async copy fp16 [128 x 32] tile (pitch PT)
__device__ __forceinline__ void async_b(int tid, const hf* __restrict__ G, int ld,
                                        int row0, int k0, hf* dst){
    #pragma unroll
    for (int i = 0; i < 2; i++) {
        int e = tid + i*256;
        int rr = e >> 2, o = e & 3;
        __pipeline_memcpy_async(dst + rr*PT + o*8,
                                G + (size_t)(row0+rr)*ld + k0 + o*8, 16);
    }
}
// async copy fp16 [32 x 64] V tile (pitch PV)
__device__ __forceinline__ void async_v(int tid, const hf* __restrict__ G,
                                        int k0, hf* dst){
    int rr = tid >> 3, o = tid & 7;
    __pipeline_memcpy_async(dst + rr*PV + o*8,
                            G + (size_t)(k0+rr)*DH_ + o*8, 16);
}

// ============================================================================
// Weight split+transpose: all 4 weights in one launch
// ============================================================================
__global__ __launch_bounds__(256) void split_w4_kernel(
    const float* __restrict__ W0, const float* __restrict__ W1,
    const float* __restrict__ W2, const float* __restrict__ W3,
    hf* __restrict__ ohBase, hf* __restrict__ olBase)
{
    const int z = blockIdx.z;
    const float* W = (z == 0) ? W0 : (z == 1) ? W1 : (z == 2) ? W2 : W3;
    hf* oh = ohBase + (size_t)z * D_ * D_;
    hf* ol = olBase + (size_t)z * D_ * D_;
    __shared__ float s[32][33];
    const int bk = blockIdx.x*32, bn = blockIdx.y*32;
    const int tx = threadIdx.x & 31, ty = threadIdx.x >> 5;
    #pragma unroll
    for (int i = 0; i < 4; i++)
        s[ty + i*8][tx] = W[(size_t)(bk + ty + i*8)*D_ + bn + tx];
    __syncthreads();
    #pragma unroll
    for (int i = 0; i < 4; i++) {
        float v = s[tx][ty + i*8];
        unsigned short h, l; split1h(v, h, l);
        size_t a = (size_t)(bn + ty + i*8)*D_ + bk + tx;
        oh[a] = __ushort_as_half(h);
        ol[a] = __ushort_as_half(l);
    }
}

// ============================================================================
// Q+K projections fused (3-term fp16, hi/lo out), A smem double-buffered
// ============================================================================
__global__ __launch_bounds__(256, 2) void proj_qk(
    const float* __restrict__ qin, const float* __restrict__ kin,
    const hf* __restrict__ Wth0, const hf* __restrict__ Wtl0,
    const hf* __restrict__ Wth1, const hf* __restrict__ Wtl1,
    const float* __restrict__ bq, const float* __restrict__ bk,
    hf* __restrict__ Qh, hf* __restrict__ Ql,
    hf* __restrict__ Kh, hf* __restrict__ Kl)
{
    const int z = blockIdx.z;
    const float* X   = z ? kin  : qin;
    const hf* Wth    = z ? Wth1 : Wth0;
    const hf* Wtl    = z ? Wtl1 : Wtl0;
    const float* bias= z ? bk   : bq;
    hf* outH         = z ? Kh   : Qh;
    hf* outL         = z ? Kl   : Ql;

    extern __shared__ char sm[];
    const int BT = 128*PT;
    hf* Ah0 = (hf*)sm;
    hf* Al0 = Ah0 + BT;
    hf* Ah1 = Al0 + BT;
    hf* Al1 = Ah1 + BT;
    hf* Bh0 = Al1 + BT;
    hf* Bl0 = Bh0 + BT;
    hf* Bh1 = Bl0 + BT;
    hf* Bl1 = Bh1 + BT;
    const int tid = threadIdx.x, w = tid >> 5, lid = tid & 31;
    const int wm = w >> 2, wn = w & 3;
    const int bm = blockIdx.y * 128, bn = blockIdx.x * 128;

    wmma::fragment<wmma::accumulator, 16, 16, 16, float> acc[4][2];
    #pragma unroll
    for (int i = 0; i < 4; i++)
        #pragma unroll
        for (int j = 0; j < 2; j++)
            wmma::fill_fragment(acc[i][j], 0.0f);

    async_b(tid, Wth, D_, bn, 0, Bh0);
    async_b(tid, Wtl, D_, bn, 0, Bl0);
    __pipeline_commit();
    ARegs ra;
    fetch_a(ra, X, D_, bm, 0, tid);
    store_a_split(ra, Ah0, Al0, tid);
    __pipeline_wait_prior(0);
    __syncthreads();
    fetch_a(ra, X, D_, bm, 32, tid);

    for (int t = 0; t < 32; t++) {
        hf* Ahc = (t & 1) ? Ah1 : Ah0;
        hf* Alc = (t & 1) ? Al1 : Al0;
        hf* Bhc = (t & 1) ? Bh1 : Bh0;
        hf* Blc = (t & 1) ? Bl1 : Bl0;
        if (t+1 < 32) {
            hf* Bhn = (t & 1) ? Bh0 : Bh1;
            hf* Bln = (t & 1) ? Bl0 : Bl1;
            async_b(tid, Wth, D_, bn, (t+1)*32, Bhn);
            async_b(tid, Wtl, D_, bn, (t+1)*32, Bln);
            __pipeline_commit();
            hf* Ahn = (t & 1) ? Ah0 : Ah1;
            hf* Aln = (t & 1) ? Al0 : Al1;
            store_a_split(ra, Ahn, Aln, tid);
        }

        #pragma unroll
        for (int ks = 0; ks < 32; ks += 16) {
            wmma::fragment<wmma::matrix_b, 16, 16, 16, hf, wmma::col_major> fbh[2], fbl[2];
            #pragma unroll
            for (int j = 0; j < 2; j++) {
                wmma::load_matrix_sync(fbh[j], Bhc + (wn*32 + j*16)*PT + ks, PT);
                wmma::load_matrix_sync(fbl[j], Blc + (wn*32 + j*16)*PT + ks, PT);
            }
            #pragma unroll
            for (int i = 0; i < 4; i++) {
                wmma::fragment<wmma::matrix_a, 16, 16, 16, hf, wmma::row_major> fah, fal;
                wmma::load_matrix_sync(fah, Ahc + (wm*64 + i*16)*PT + ks, PT);
                wmma::load_matrix_sync(fal, Alc + (wm*64 + i*16)*PT + ks, PT);
                #pragma unroll
                for (int j = 0; j < 2; j++) {
                    wmma::mma_sync(acc[i][j], fah, fbh[j], acc[i][j]);
                    wmma::mma_sync(acc[i][j], fah, fbl[j], acc[i][j]);
                    wmma::mma_sync(acc[i][j], fal, fbh[j], acc[i][j]);
                }
            }
        }
        if (t+1 < 32) {
            __pipeline_wait_prior(0);
            __syncthreads();
            if (t+2 < 32) fetch_a(ra, X, D_, bm, (t+2)*32, tid);
        }
    }
    __syncthreads();

    float* ws = (float*)sm + w * (16*24);
    hf* SH = (hf*)(sm + 12288);
    hf* SL = (hf*)(sm + 12288 + 34816);
    #pragma unroll
    for (int i = 0; i < 4; i++) {
        #pragma unroll
        for (int j = 0; j < 2; j++) {
            wmma::store_matrix_sync(ws, acc[i][j], 24, wmma::mem_row_major);
            __syncwarp();
            #pragma unroll
            for (int tt = 0; tt < 8; tt++) {
                int e = lid + tt*32, r = e >> 4, c = e & 15;
                int row = wm*64 + i*16 + r;
                int col = wn*32 + j*16 + c;
                float v = ws[r*24 + c] + bias[bn + col];
                unsigned short hs, ls; split1h(v, hs, ls);
                SH[row*136 + col] = __ushort_as_half(hs);
                SL[row*136 + col] = __ushort_as_half(ls);
            }
            __syncwarp();
        }
    }
    __syncthreads();
    #pragma unroll
    for (int q = 0; q < 8; q++) {
        int e = tid + q*256;
        int rr = e >> 4, o = e & 15;
        int m = bm + rr, bb = m >> 11, l = m & (L_-1);
        int n0 = bn + o*8, h = n0 >> 6, dh = n0 & 63;
        size_t a = (((size_t)(bb*H_ + h))*L_ + l)*DH_ + dh;
        *(uint4*)(outH + a) = *(uint4*)(&SH[rr*136 + o*8]);
        *(uint4*)(outL + a) = *(uint4*)(&SL[rr*136 + o*8]);
    }
}

// ============================================================================
// V projection (1-term, fp16 out), A smem double-buffered
// ============================================================================
__global__ __launch_bounds__(256, 2) void proj_v(
    const float* __restrict__ X,
    const hf* __restrict__ Wth, const float* __restrict__ bias,
    hf* __restrict__ outH)
{
    extern __shared__ char sm[];
    const int BT = 128*PT;
    hf* Ah0 = (hf*)sm;
    hf* Ah1 = Ah0 + BT;
    hf* Bh0 = Ah1 + BT;
    hf* Bh1 = Bh0 + BT;
    const int tid = threadIdx.x, w = tid >> 5, lid = tid & 31;
    const int wm = w >> 2, wn = w & 3;
    const int bm = blockIdx.y * 128, bn = blockIdx.x * 128;

    wmma::fragment<wmma::accumulator, 16, 16, 16, float> acc[4][2];
    #pragma unroll
    for (int i = 0; i < 4; i++)
        #pragma unroll
        for (int j = 0; j < 2; j++)
            wmma::fill_fragment(acc[i][j], 0.0f);

    async_b(tid, Wth, D_, bn, 0, Bh0);
    __pipeline_commit();
    ARegs ra;
    fetch_a(ra, X, D_, bm, 0, tid);
    store_a_round(ra, Ah0, tid);
    __pipeline_wait_prior(0);
    __syncthreads();
    fetch_a(ra, X, D_, bm, 32, tid);

    for (int t = 0; t < 32; t++) {
        hf* Ahc = (t & 1) ? Ah1 : Ah0;
        hf* Bhc = (t & 1) ? Bh1 : Bh0;
        if (t+1 < 32) {
            hf* Bhn = (t & 1) ? Bh0 : Bh1;
            async_b(tid, Wth, D_, bn, (t+1)*32, Bhn);
            __pipeline_commit();
            hf* Ahn = (t & 1) ? Ah0 : Ah1;
            store_a_round(ra, Ahn, tid);
        }

        #pragma unroll
        for (int ks = 0; ks < 32; ks += 16) {
            wmma::fragment<wmma::matrix_b, 16, 16, 16, hf, wmma::col_major> fbh[2];
            #pragma unroll
            for (int j = 0; j < 2; j++)
                wmma::load_matrix_sync(fbh[j], Bhc + (wn*32 + j*16)*PT + ks, PT);
            #pragma unroll
            for (int i = 0; i < 4; i++) {
                wmma::fragment<wmma::matrix_a, 16, 16, 16, hf, wmma::row_major> fah;
                wmma::load_matrix_sync(fah, Ahc + (wm*64 + i*16)*PT + ks, PT);
                #pragma unroll
                for (int j = 0; j < 2; j++)
                    wmma::mma_sync(acc[i][j], fah, fbh[j], acc[i][j]);
            }
        }
        if (t+1 < 32) {
            __pipeline_wait_prior(0);
            __syncthreads();
            if (t+2 < 32) fetch_a(ra, X, D_, bm, (t+2)*32, tid);
        }
    }
    __syncthreads();

    float* ws = (float*)sm + w * (16*24);
    hf* SH = (hf*)(sm + 12288);
    #pragma unroll
    for (int i = 0; i < 4; i++) {
        #pragma unroll
        for (int j = 0; j < 2; j++) {
            wmma::store_matrix_sync(ws, acc[i][j], 24, wmma::mem_row_major);
            __syncwarp();
            #pragma unroll
            for (int tt = 0; tt < 8; tt++) {
                int e = lid + tt*32, r = e >> 4, c = e & 15;
                int row = wm*64 + i*16 + r;
                int col = wn*32 + j*16 + c;
                SH[row*136 + col] = __float2half_rn(ws[r*24 + c] + bias[bn + col]);
            }
            __syncwarp();
        }
    }
    __syncthreads();
    #pragma unroll
    for (int q = 0; q < 8; q++) {
        int e = tid + q*256;
        int rr = e >> 4, o = e & 15;
        int m = bm + rr, bb = m >> 11, l = m & (L_-1);
        int n0 = bn + o*8, h = n0 >> 6, dh = n0 & 63;
        size_t a = (((size_t)(bb*H_ + h))*L_ + l)*DH_ + dh;
        *(uint4*)(outH + a) = *(uint4*)(&SH[rr*136 + o*8]);
    }
}

// ============================================================================
// Scores: 3-term fp16, DOUBLE-BUFFERED k-chunks (both loads issued up front)
// ============================================================================
__global__ __launch_bounds__(256, 2) void scores_mma(float* __restrict__ attn)
{
    extern __shared__ char sm[];
    const int BT = 128*PT;
    hf* T[8];    // [chunk][operand]: Ah,Al,Bh,Bl for chunk0 then chunk1
    #pragma unroll
    for (int i = 0; i < 8; i++) T[i] = (hf*)sm + i*BT;
    const int tid = threadIdx.x, w = tid >> 5, lid = tid & 31;
    const int wm = w >> 2, wn = w & 3;
    const int bh = blockIdx.z, bm = blockIdx.y * 128, bn = blockIdx.x * 128;
    const size_t qo = (size_t)bh * L_ * DH_;

    wmma::fragment<wmma::accumulator, 16, 16, 16, float> acc[4][2];
    #pragma unroll
    for (int i = 0; i < 4; i++)
        #pragma unroll
        for (int j = 0; j < 2; j++)
            wmma::fill_fragment(acc[i][j], 0.0f);

    // issue BOTH k-chunk loads before any MMA
    #pragma unroll
    for (int t = 0; t < 2; t++) {
        async_b(tid, g_Qh + qo, DH_, bm, t*32, T[t*4+0]);
        async_b(tid, g_Ql + qo, DH_, bm, t*32, T[t*4+1]);
        async_b(tid, g_Kh + qo, DH_, bn, t*32, T[t*4+2]);
        async_b(tid, g_Kl + qo, DH_, bn, t*32, T[t*4+3]);
        __pipeline_commit();
    }

    #pragma unroll
    for (int t = 0; t < 2; t++) {
        if (t == 0) __pipeline_wait_prior(1);
        else        __pipeline_wait_prior(0);
        __syncthreads();
        hf* Ah = T[t*4+0];
        hf* Al = T[t*4+1];
        hf* Bh = T[t*4+2];
        hf* Bl = T[t*4+3];
        #pragma unroll
        for (int ks = 0; ks < 32; ks += 16) {
            wmma::fragment<wmma::matrix_b, 16, 16, 16, hf, wmma::col_major> fbh[2], fbl[2];
            #pragma unroll
            for (int j = 0; j < 2; j++) {
                wmma::load_matrix_sync(fbh[j], Bh + (wn*32 + j*16)*PT + ks, PT);
                wmma::load_matrix_sync(fbl[j], Bl + (wn*32 + j*16)*PT + ks, PT);
            }
            #pragma unroll
            for (int i = 0; i < 4; i++) {
                wmma::fragment<wmma::matrix_a, 16, 16, 16, hf, wmma::row_major> fah, fal;
                wmma::load_matrix_sync(fah, Ah + (wm*64 + i*16)*PT + ks, PT);
                wmma::load_matrix_sync(fal, Al + (wm*64 + i*16)*PT + ks, PT);
                #pragma unroll
                for (int j = 0; j < 2; j++) {
                    wmma::mma_sync(acc[i][j], fah, fbh[j], acc[i][j]);
                    wmma::mma_sync(acc[i][j], fah, fbl[j], acc[i][j]);
                    wmma::mma_sync(acc[i][j], fal, fbh[j], acc[i][j]);
                }
            }
        }
    }
    __syncthreads();

    float* ws = (float*)sm + w * (16*24);
    #pragma unroll
    for (int i = 0; i < 4; i++) {
        #pragma unroll
        for (int j = 0; j < 2; j++) {
            wmma::store_matrix_sync(ws, acc[i][j], 24, wmma::mem_row_major);
            __syncwarp();
            #pragma unroll
            for (int tt = 0; tt < 2; tt++) {
                int idx = lid + tt*32;
                int r = idx >> 2, c4 = (idx & 3) << 2;
                float4 v = *(float4*)(&ws[r*24 + c4]);
                v.x *= SCALE; v.y *= SCALE; v.z *= SCALE; v.w *= SCALE;
                int m = bm + wm*64 + i*16 + r;
                int n = bn + wn*32 + j*16 + c4;
                *(float4*)(&attn[((size_t)bh*L_ + m)*L_ + n]) = v;
            }
            __syncwarp();
        }
    }
}

// ============================================================================
// Softmax: fp32 in-place (streaming) + fp16 copy for PV
// ============================================================================
__global__ __launch_bounds__(256) void softmax_kernel(float* __restrict__ attn,
                                                      hf* __restrict__ attn16)
{
    float4* p = (float4*)(attn + (size_t)blockIdx.x * L_);
    hf* p16 = attn16 + (size_t)blockIdx.x * L_;
    const int t = threadIdx.x;
    float4 a = p[t], b = p[t + 256];
    float m = fmaxf(fmaxf(fmaxf(a.x,a.y),fmaxf(a.z,a.w)),
                    fmaxf(fmaxf(b.x,b.y),fmaxf(b.z,b.w)));
    #pragma unroll
    for (int o = 16; o; o >>= 1) m = fmaxf(m, __shfl_xor_sync(0xffffffffu, m, o));
    __shared__ float redm[8], reds[8];
    if ((t & 31) == 0) redm[t >> 5] = m;
    __syncthreads();
    float bm = redm[0];
    #pragma unroll
    for (int q = 1; q < 8; q++) bm = fmaxf(bm, redm[q]);
    a.x = __expf(a.x - bm); a.y = __expf(a.y - bm);
    a.z = __expf(a.z - bm); a.w = __expf(a.w - bm);
    b.x = __expf(b.x - bm); b.y = __expf(b.y - bm);
    b.z = __expf(b.z - bm); b.w = __expf(b.w - bm);
    float s = a.x + a.y + a.z + a.w + b.x + b.y + b.z + b.w;
    #pragma unroll
    for (int o = 16; o; o >>= 1) s += __shfl_xor_sync(0xffffffffu, s, o);
    if ((t & 31) == 0) reds[t >> 5] = s;
    __syncthreads();
    float bs = 0.f;
    #pragma unroll
    for (int q = 0; q < 8; q++) bs += reds[q];
    float inv = 1.0f / bs;
    a.x *= inv; a.y *= inv; a.z *= inv; a.w *= inv;
    b.x *= inv; b.y *= inv; b.z *= inv; b.w *= inv;
    __stwt(&p[t], a);
    __stwt(&p[t + 256], b);
    __half2 h0 = __floats2half2_rn(a.x, a.y);
    __half2 h1 = __floats2half2_rn(a.z, a.w);
    __half2 h2 = __floats2half2_rn(b.x, b.y);
    __half2 h3 = __floats2half2_rn(b.z, b.w);
    uint2 u0; u0.x = *(uint32_t*)&h0; u0.y = *(uint32_t*)&h1;
    uint2 u1; u1.x = *(uint32_t*)&h2; u1.y = *(uint32_t*)&h3;
    *(uint2*)(p16 + t*4)         = u0;
    *(uint2*)(p16 + (t + 256)*4) = u1;
}

// ============================================================================
// PV: all-fp16 async pipeline
// ============================================================================
__global__ __launch_bounds__(256, 2) void pv_mma()
{
    extern __shared__ char sm[];
    hf* Ph0 = (hf*)sm;
    hf* Ph1 = Ph0 + 128*PT;
    hf* Vh0 = Ph1 + 128*PT;
    hf* Vh1 = Vh0 + 32*PV;
    const int tid = threadIdx.x, w = tid >> 5, lid = tid & 31;
    const int wm = w >> 1, wn = w & 1;
    const int bh = blockIdx.y, bm = blockIdx.x * 128;
    const hf* A16 = g_attnh + (size_t)bh * L_ * L_;
    const hf* Vg = g_V + (size_t)bh * L_ * DH_;

    wmma::fragment<wmma::accumulator, 16, 16, 16, float> acc[2][2];
    #pragma unroll
    for (int i = 0; i < 2; i++)
        #pragma unroll
        for (int j = 0; j < 2; j++)
            wmma::fill_fragment(acc[i][j], 0.0f);

    async_b(tid, A16, L_, bm, 0, Ph0);
    async_v(tid, Vg, 0, Vh0);
    __pipeline_commit();

    for (int t = 0; t < 64; t++) {
        hf* Pc = (t & 1) ? Ph1 : Ph0;
        hf* Vc = (t & 1) ? Vh1 : Vh0;
        if (t+1 < 64) {
            hf* Pn = (t & 1) ? Ph0 : Ph1;
            hf* Vn = (t & 1) ? Vh0 : Vh1;
            async_b(tid, A16, L_, bm, (t+1)*32, Pn);
            async_v(tid, Vg, (t+1)*32, Vn);
            __pipeline_commit();
        }
        if (t+1 < 64) __pipeline_wait_prior(1);
        else          __pipeline_wait_prior(0);
        __syncthreads();

        #pragma unroll
        for (int ks = 0; ks < 32; ks += 16) {
            wmma::fragment<wmma::matrix_b, 16, 16, 16, hf, wmma::row_major> fbh[2];
            #pragma unroll
            for (int j = 0; j < 2; j++)
                wmma::load_matrix_sync(fbh[j], Vc + ks*PV + wn*32 + j*16, PV);
            #pragma unroll
            for (int i = 0; i < 2; i++) {
                wmma::fragment<wmma::matrix_a, 16, 16, 16, hf, wmma::row_major> fah;
                wmma::load_matrix_sync(fah, Pc + (wm*32 + i*16)*PT + ks, PT);
                #pragma unroll
                for (int j = 0; j < 2; j++)
                    wmma::mma_sync(acc[i][j], fah, fbh[j], acc[i][j]);
            }
        }
        __syncthreads();
    }

    float* ws = (float*)sm + w * (16*24);
    hf* SO = (hf*)(sm + 12288);
    #pragma unroll
    for (int i = 0; i < 2; i++) {
        #pragma unroll
        for (int j = 0; j < 2; j++) {
            wmma::store_matrix_sync(ws, acc[i][j], 24, wmma::mem_row_major);
            __syncwarp();
            #pragma unroll
            for (int tt = 0; tt < 8; tt++) {
                int e = lid + tt*32, r = e >> 4, c = e & 15;
                int row = wm*32 + i*16 + r;
                int col = wn*32 + j*16 + c;
                SO[row*72 + col] = __float2half_rn(ws[r*24 + c]);
            }
            __syncwarp();
        }
    }
    __syncthreads();
    const int b = bh >> 4, h = bh & 15;
    #pragma unroll
    for (int q = 0; q < 4; q++) {
        int e = tid + q*256;
        int rr = e >> 3, o = e & 7;
        *(uint4*)(&g_Oh[((size_t)(b*L_ + bm + rr))*D_ + h*DH_ + o*8]) =
            *(uint4*)(&SO[rr*72 + o*8]);
    }
}

// ============================================================================
// Output projection: fully async fp16 A/B
// ============================================================================
__global__ __launch_bounds__(256, 2) void out_proj(
    const hf* __restrict__ Wth, const float* __restrict__ bias,
    float* __restrict__ outF)
{
    extern __shared__ char sm[];
    const int BT = 128*PT;
    hf* Ah0 = (hf*)sm;
    hf* Ah1 = Ah0 + BT;
    hf* Bh0 = Ah1 + BT;
    hf* Bh1 = Bh0 + BT;
    const int tid = threadIdx.x, w = tid >> 5, lid = tid & 31;
    const int wm = w >> 2, wn = w & 3;
    const int bm = blockIdx.y * 128, bn = blockIdx.x * 128;

    wmma::fragment<wmma::accumulator, 16, 16, 16, float> acc[4][2];
    #pragma unroll
    for (int i = 0; i < 4; i++)
        #pragma unroll
        for (int j = 0; j < 2; j++)
            wmma::fill_fragment(acc[i][j], 0.0f);

    async_b(tid, g_Oh, D_, bm, 0, Ah0);
    async_b(tid, Wth, D_, bn, 0, Bh0);
    __pipeline_commit();

    for (int t = 0; t < 32; t++) {
        hf* Ac = (t & 1) ? Ah1 : Ah0;
        hf* Bc = (t & 1) ? Bh1 : Bh0;
        if (t+1 < 32) {
            hf* An = (t & 1) ? Ah0 : Ah1;
            hf* Bn = (t & 1) ? Bh0 : Bh1;
            async_b(tid, g_Oh, D_, bm, (t+1)*32, An);
            async_b(tid, Wth, D_, bn, (t+1)*32, Bn);
            __pipeline_commit();
        }
        if (t+1 < 32) __pipeline_wait_prior(1);
        else          __pipeline_wait_prior(0);
        __syncthreads();

        #pragma unroll
        for (int ks = 0; ks < 32; ks += 16) {
            wmma::fragment<wmma::matrix_b, 16, 16, 16, hf, wmma::col_major> fbh[2];
            #pragma unroll
            for (int j = 0; j < 2; j++)
                wmma::load_matrix_sync(fbh[j], Bc + (wn*32 + j*16)*PT + ks, PT);
            #pragma unroll
            for (int i = 0; i < 4; i++) {
                wmma::fragment<wmma::matrix_a, 16, 16, 16, hf, wmma::row_major> fah;
                wmma::load_matrix_sync(fah, Ac + (wm*64 + i*16)*PT + ks, PT);
                #pragma unroll
                for (int j = 0; j < 2; j++)
                    wmma::mma_sync(acc[i][j], fah, fbh[j], acc[i][j]);
            }
        }
        __syncthreads();
    }

    float* ws = (float*)sm + w * (16*24);
    float* SF = (float*)(sm + 12288);
    #pragma unroll
    for (int i = 0; i < 4; i++) {
        #pragma unroll
        for (int j = 0; j < 2; j++) {
            wmma::store_matrix_sync(ws, acc[i][j], 24, wmma::mem_row_major);
            __syncwarp();
            #pragma unroll
            for (int tt = 0; tt < 8; tt++) {
                int e = lid + tt*32, r = e >> 4, c = e & 15;
                int row = wm*64 + i*16 + r;
                int col = wn*32 + j*16 + c;
                SF[row*132 + col] = ws[r*24 + c] + bias[bn + col];
            }
            __syncwarp();
        }
    }
    __syncthreads();
    #pragma unroll
    for (int q = 0; q < 16; q++) {
        int e = tid + q*256;
        int rr = e >> 5, o = e & 31;
        *(float4*)(outF + (size_t)(bm+rr)*D_ + bn + o*4) = *(float4*)(&SF[rr*132 + o*4]);
    }
}

// ============================================================================
extern "C" void kernel_launch(void* const* d_in, const int* in_sizes, int n_in,
                              void* d_out, int out_size)
{
    const float* q  = (const float*)d_in[0];
    const float* k  = (const float*)d_in[1];
    const float* v  = (const float*)d_in[2];
    const float* Wq = (const float*)d_in[3];
    const float* bq = (const float*)d_in[4];
    const float* Wk = (const float*)d_in[5];
    const float* bk = (const float*)d_in[6];
    const float* Wv = (const float*)d_in[7];
    const float* bv = (const float*)d_in[8];
    const float* Wo = (const float*)d_in[9];
    const float* bo = (const float*)d_in[10];
    float* out = (float*)d_out;

    float *pAttnFb;
    hf *pQh,*pQl,*pKh,*pKl,*pV,*pWth,*pWtl,*pAttn16;
    cudaGetSymbolAddress((void**)&pAttnFb, g_attn_fallback);
    cudaGetSymbolAddress((void**)&pQh, g_Qh);
    cudaGetSymbolAddress((void**)&pQl, g_Ql);
    cudaGetSymbolAddress((void**)&pKh, g_Kh);
    cudaGetSymbolAddress((void**)&pKl, g_Kl);
    cudaGetSymbolAddress((void**)&pV,  g_V);
    cudaGetSymbolAddress((void**)&pWth, g_Wth);
    cudaGetSymbolAddress((void**)&pWtl, g_Wtl);
    cudaGetSymbolAddress((void**)&pAttn16, g_attnh);

    const long long need = (long long)M_ * D_ + (long long)BH_ * L_ * L_;
    float* attn = ((long long)out_size >= need) ? (out + (size_t)M_ * D_) : pAttnFb;

    const int SM_QK     = 81920;
    const int SM_V      = 47104;
    const int SM_SCORES = 81920;   // 8 tiles double-buffered (2 CTAs/SM still fit: regs are the limit)
    const int SM_PV     = 30720;
    const int SM_OUT    = 79872;

    cudaFuncSetAttribute(proj_qk,    cudaFuncAttributeMaxDynamicSharedMemorySize, SM_QK);
    cudaFuncSetAttribute(proj_v,     cudaFuncAttributeMaxDynamicSharedMemorySize, SM_V);
    cudaFuncSetAttribute(scores_mma, cudaFuncAttributeMaxDynamicSharedMemorySize, SM_SCORES);
    cudaFuncSetAttribute(pv_mma,     cudaFuncAttributeMaxDynamicSharedMemorySize, SM_PV);
    cudaFuncSetAttribute(out_proj,   cudaFuncAttributeMaxDynamicSharedMemorySize, SM_OUT);

    const size_t WSZ = (size_t)D_ * D_;
    dim3 gW(D_/32, D_/32, 4);
    split_w4_kernel<<<gW, 256>>>(Wq, Wk, Wv, Wo, pWth, pWtl);

    dim3 gQK(D_/128, M_/128, 2);
    proj_qk<<<gQK, 256, SM_QK>>>(q, k, pWth + 0*WSZ, pWtl + 0*WSZ,
                                 pWth + 1*WSZ, pWtl + 1*WSZ,
                                 bq, bk, pQh, pQl, pKh, pKl);

    dim3 gProj(D_/128, M_/128);
    proj_v<<<gProj, 256, SM_V>>>(v, pWth + 2*WSZ, bv, pV);

    dim3 gS(L_/128, L_/128, BH_);
    scores_mma<<<gS, 256, SM_SCORES>>>(attn);

    softmax_kernel<<<BH_*L_, 256>>>(attn, pAttn16);

    dim3 gPV(L_/128, BH_);
    pv_mma<<<gPV, 256, SM_PV>>>();

    out_proj<<<gProj, 256, SM_OUT>>>(pWth + 3*WSZ, bo, out);
}